// round 15
// baseline (speedup 1.0000x reference)
#include <cuda_runtime.h>
#include <cuda_bf16.h>
#include <math.h>

// Problem constants
#define BB 32        // batch
#define TT 64        // time steps (MAX_LENGTH)
#define HH 1024      // hidden
#define VV 32000     // vocab
#define BT 2048      // BB*TT
#define TH 3072      // 3*HH
#define K2H 512      // HH/2  (u32 words per bf16 row of length HH)

// ---------------- device scratch (static, no allocation) ----------------
__device__ __nv_bfloat16 g_X_hi[(size_t)BT * HH];   // relu(emb[tok]) bf16 hi
__device__ __nv_bfloat16 g_X_lo[(size_t)BT * HH];   // residual lo
__device__ __nv_bfloat16 g_Wih_hi[(size_t)TH * HH];
__device__ __nv_bfloat16 g_Wih_lo[(size_t)TH * HH];
__device__ __nv_bfloat16 g_Whh_hi[(size_t)TH * HH];
__device__ __nv_bfloat16 g_Whh_lo[(size_t)TH * HH];
__device__ __nv_bfloat16 g_fcw[(size_t)VV * HH];    // fc_w bf16 (single — output0 has margin)
__device__ float         g_GI[(size_t)BT * TH];     // precomputed gi (fp32)
__device__ __nv_bfloat16 g_HS[(size_t)BT * HH];     // h states bf16 (classifier A)
__device__ float         g_h[2][BB * HH];           // h double buffer fp32
__device__ __nv_bfloat16 g_hb_hi[2][BB * HH];       // h double buffer bf16 hi
__device__ __nv_bfloat16 g_hb_lo[2][BB * HH];       // h double buffer bf16 lo
__device__ int           g_tok[BB * TT];            // canonicalized tokens
__device__ unsigned      g_bar;                     // grid barrier counter

// ---------------- bf16 mma.sync m16n8k16 helper ----------------
__device__ __forceinline__ void mma16816(float c[4], const unsigned a[4], const unsigned b[2]) {
    asm volatile(
        "mma.sync.aligned.m16n8k16.row.col.f32.bf16.bf16.f32 "
        "{%0,%1,%2,%3}, {%4,%5,%6,%7}, {%8,%9}, {%0,%1,%2,%3};\n"
        : "+f"(c[0]), "+f"(c[1]), "+f"(c[2]), "+f"(c[3])
        : "r"(a[0]), "r"(a[1]), "r"(a[2]), "r"(a[3]), "r"(b[0]), "r"(b[1]));
}

// ---------------- kernel 0: token canonicalization (int32 vs int64 detect) ----
__global__ void k_tok(const int* __restrict__ tgt32) {
    __shared__ int nz;
    if (threadIdx.x == 0) { nz = 0; g_bar = 0; }
    __syncthreads();
    for (int i = threadIdx.x; i < BT / 2; i += blockDim.x)
        if (tgt32[2 * i + 1] != 0) atomicOr(&nz, 1);
    __syncthreads();
    bool is64 = (nz == 0);
    for (int i = threadIdx.x; i < BT; i += blockDim.x) {
        int v = is64 ? tgt32[2 * i] : tgt32[i];
        g_tok[i] = min(max(v, 0), VV - 1);
    }
}

// ---------------- kernel 1: fp32 -> bf16 (hi/lo split) weight conversion ------
__global__ void k_convert(const float* __restrict__ Wih,
                          const float* __restrict__ Whh,
                          const float* __restrict__ fcw) {
    const int NW = TH * HH;
    const int NF = VV * HH;
    int stride = gridDim.x * blockDim.x;
    for (int i = blockIdx.x * blockDim.x + threadIdx.x; i < NW; i += stride) {
        float w1 = Wih[i];
        __nv_bfloat16 h1 = __float2bfloat16(w1);
        g_Wih_hi[i] = h1;
        g_Wih_lo[i] = __float2bfloat16(w1 - __bfloat162float(h1));
        float w2 = Whh[i];
        __nv_bfloat16 h2 = __float2bfloat16(w2);
        g_Whh_hi[i] = h2;
        g_Whh_lo[i] = __float2bfloat16(w2 - __bfloat162float(h2));
    }
    for (int i = blockIdx.x * blockDim.x + threadIdx.x; i < NF; i += stride)
        g_fcw[i] = __float2bfloat16(fcw[i]);
}

// ---------------- kernel 2: embedding gather + relu (split) + h0 init ---------
__global__ void k_embed(const float* __restrict__ emb,
                        const float* __restrict__ ench) {
    int i = blockIdx.x;
    if (i < BT) {
        int t = i >> 5, b = i & 31;  // row i = t*32 + b
        int tok = (t == 0) ? 0 : g_tok[b * TT + (t - 1)];
        const float* e = emb + (size_t)tok * HH;
        for (int c = threadIdx.x; c < HH; c += blockDim.x) {
            float x = fmaxf(e[c], 0.f);
            __nv_bfloat16 hi = __float2bfloat16(x);
            g_X_hi[(size_t)i * HH + c] = hi;
            g_X_lo[(size_t)i * HH + c] = __float2bfloat16(x - __bfloat162float(hi));
        }
    } else {
        int b = i - BT;
        for (int c = threadIdx.x; c < HH; c += blockDim.x) {
            float v = ench[b * HH + c];
            g_h[0][b * HH + c] = v;
            __nv_bfloat16 hi = __float2bfloat16(v);
            g_hb_hi[0][b * HH + c] = hi;
            g_hb_lo[0][b * HH + c] = __float2bfloat16(v - __bfloat162float(hi));
        }
    }
}

// ---------------- kernel 3: GI GEMM, split-bf16 (3-MMA compensation) ----------
// GI = X @ W_ih^T + b_ih   (M=2048, N=3072, K=1024), near-fp32 precision:
//   C = Xhi*Whi + Xlo*Whi + Xhi*Wlo
__global__ void __launch_bounds__(256) k_gemm_gi(const float* __restrict__ bias) {
    __shared__ unsigned AhU[128 * 17];
    __shared__ unsigned AlU[128 * 17];
    __shared__ unsigned BhU[128 * 17];
    __shared__ unsigned BlU[128 * 17];

    const int tid  = threadIdx.x;
    const int warp = tid >> 5, lane = tid & 31;
    const int wm = warp >> 1, wn = warp & 1;
    const int group = lane >> 2, tig = lane & 3;

    const unsigned* Agh = reinterpret_cast<const unsigned*>(g_X_hi)   + (size_t)blockIdx.x * 128 * K2H;
    const unsigned* Agl = reinterpret_cast<const unsigned*>(g_X_lo)   + (size_t)blockIdx.x * 128 * K2H;
    const unsigned* Bgh = reinterpret_cast<const unsigned*>(g_Wih_hi) + (size_t)blockIdx.y * 128 * K2H;
    const unsigned* Bgl = reinterpret_cast<const unsigned*>(g_Wih_lo) + (size_t)blockIdx.y * 128 * K2H;

    float c[2][8][4];
#pragma unroll
    for (int mt = 0; mt < 2; mt++)
#pragma unroll
        for (int nt = 0; nt < 8; nt++)
#pragma unroll
            for (int q = 0; q < 4; q++) c[mt][nt][q] = 0.f;

    for (int k0 = 0; k0 < K2H; k0 += 16) {  // BK = 32 bf16 = 16 u32
#pragma unroll
        for (int q = 0; q < 8; q++) {
            int idx = tid + q * 256;
            int r = idx >> 4, cw = idx & 15;
            size_t go = (size_t)r * K2H + k0 + cw;
            int so = r * 17 + cw;
            AhU[so] = Agh[go];
            AlU[so] = Agl[go];
            BhU[so] = Bgh[go];
            BlU[so] = Bgl[go];
        }
        __syncthreads();
#pragma unroll
        for (int kk = 0; kk < 2; kk++) {
            int k2 = kk * 8;
            unsigned ah[2][4], al[2][4], b[8][2];
#pragma unroll
            for (int mt = 0; mt < 2; mt++) {
                int r0 = (wm * 32 + mt * 16 + group) * 17 + k2 + tig;
                ah[mt][0] = AhU[r0];
                ah[mt][1] = AhU[r0 + 8 * 17];
                ah[mt][2] = AhU[r0 + 4];
                ah[mt][3] = AhU[r0 + 8 * 17 + 4];
                al[mt][0] = AlU[r0];
                al[mt][1] = AlU[r0 + 8 * 17];
                al[mt][2] = AlU[r0 + 4];
                al[mt][3] = AlU[r0 + 8 * 17 + 4];
            }
            // pass 1+2: b = W_hi -> Xhi*Whi + Xlo*Whi
#pragma unroll
            for (int nt = 0; nt < 8; nt++) {
                int r = (wn * 64 + nt * 8 + group) * 17 + k2 + tig;
                b[nt][0] = BhU[r];
                b[nt][1] = BhU[r + 4];
            }
#pragma unroll
            for (int mt = 0; mt < 2; mt++)
#pragma unroll
                for (int nt = 0; nt < 8; nt++) {
                    mma16816(c[mt][nt], ah[mt], b[nt]);
                    mma16816(c[mt][nt], al[mt], b[nt]);
                }
            // pass 3: b = W_lo -> Xhi*Wlo
#pragma unroll
            for (int nt = 0; nt < 8; nt++) {
                int r = (wn * 64 + nt * 8 + group) * 17 + k2 + tig;
                b[nt][0] = BlU[r];
                b[nt][1] = BlU[r + 4];
            }
#pragma unroll
            for (int mt = 0; mt < 2; mt++)
#pragma unroll
                for (int nt = 0; nt < 8; nt++)
                    mma16816(c[mt][nt], ah[mt], b[nt]);
        }
        __syncthreads();
    }

#pragma unroll
    for (int mt = 0; mt < 2; mt++)
#pragma unroll
        for (int nt = 0; nt < 8; nt++) {
            int row = blockIdx.x * 128 + wm * 32 + mt * 16 + group;
            int col = blockIdx.y * 128 + wn * 64 + nt * 8 + tig * 2;
            float b0v = bias[col], b1v = bias[col + 1];
            *reinterpret_cast<float2*>(&g_GI[(size_t)row * TH + col]) =
                make_float2(c[mt][nt][0] + b0v, c[mt][nt][1] + b1v);
            *reinterpret_cast<float2*>(&g_GI[(size_t)(row + 8) * TH + col]) =
                make_float2(c[mt][nt][2] + b0v, c[mt][nt][3] + b1v);
        }
}

// ---------------- kernel 4: persistent GRU recurrence (64 steps, split-bf16) --
__global__ void __launch_bounds__(128) k_recurrent(const float* __restrict__ bhh,
                                                   float* __restrict__ dout) {
    const int tid = threadIdx.x, warp = tid >> 5, lane = tid & 31;
    const int group = lane >> 2, tig = lane & 3;
    const int c0 = blockIdx.x * 16;
    __shared__ float ghs[3][32][16];

    const unsigned* Wh = reinterpret_cast<const unsigned*>(g_Whh_hi);
    const unsigned* Wl = reinterpret_cast<const unsigned*>(g_Whh_lo);

    for (int t = 0; t < TT; t++) {
        int cur = t & 1;
        if (warp < 3) {
            const unsigned* hbh = reinterpret_cast<const unsigned*>(g_hb_hi[cur]);
            const unsigned* hbl = reinterpret_cast<const unsigned*>(g_hb_lo[cur]);
            float c[2][2][4];
#pragma unroll
            for (int mt = 0; mt < 2; mt++)
#pragma unroll
                for (int nt = 0; nt < 2; nt++)
#pragma unroll
                    for (int q = 0; q < 4; q++) c[mt][nt][q] = 0.f;

            int wrow0 = warp * HH + c0;  // base weight row of this gate strip
#pragma unroll 2
            for (int k2 = 0; k2 < K2H; k2 += 8) {
                unsigned ah[2][4], al[2][4], b[2][2];
#pragma unroll
                for (int mt = 0; mt < 2; mt++) {
                    int r0 = (mt * 16 + group) * K2H + k2 + tig;
                    ah[mt][0] = __ldcg(hbh + r0);
                    ah[mt][1] = __ldcg(hbh + r0 + 8 * K2H);
                    ah[mt][2] = __ldcg(hbh + r0 + 4);
                    ah[mt][3] = __ldcg(hbh + r0 + 8 * K2H + 4);
                    al[mt][0] = __ldcg(hbl + r0);
                    al[mt][1] = __ldcg(hbl + r0 + 8 * K2H);
                    al[mt][2] = __ldcg(hbl + r0 + 4);
                    al[mt][3] = __ldcg(hbl + r0 + 8 * K2H + 4);
                }
                // hi*Whi + lo*Whi
#pragma unroll
                for (int nt = 0; nt < 2; nt++) {
                    size_t r = (size_t)(wrow0 + nt * 8 + group) * K2H + k2 + tig;
                    b[nt][0] = Wh[r];
                    b[nt][1] = Wh[r + 4];
                }
#pragma unroll
                for (int mt = 0; mt < 2; mt++)
#pragma unroll
                    for (int nt = 0; nt < 2; nt++) {
                        mma16816(c[mt][nt], ah[mt], b[nt]);
                        mma16816(c[mt][nt], al[mt], b[nt]);
                    }
                // hi*Wlo
#pragma unroll
                for (int nt = 0; nt < 2; nt++) {
                    size_t r = (size_t)(wrow0 + nt * 8 + group) * K2H + k2 + tig;
                    b[nt][0] = Wl[r];
                    b[nt][1] = Wl[r + 4];
                }
#pragma unroll
                for (int mt = 0; mt < 2; mt++)
#pragma unroll
                    for (int nt = 0; nt < 2; nt++)
                        mma16816(c[mt][nt], ah[mt], b[nt]);
            }
#pragma unroll
            for (int mt = 0; mt < 2; mt++)
#pragma unroll
                for (int nt = 0; nt < 2; nt++) {
                    int row = mt * 16 + group, col = nt * 8 + tig * 2;
                    ghs[warp][row][col]         = c[mt][nt][0];
                    ghs[warp][row][col + 1]     = c[mt][nt][1];
                    ghs[warp][row + 8][col]     = c[mt][nt][2];
                    ghs[warp][row + 8][col + 1] = c[mt][nt][3];
                }
        }
        __syncthreads();

        int nxt = cur ^ 1;
#pragma unroll
        for (int q = 0; q < 4; q++) {
            int idx = tid + q * 128;
            int b_ = idx >> 4, cc = idx & 15;
            int col = c0 + cc;
            size_t gib = ((size_t)(t * BB + b_)) * TH + col;
            float rr = g_GI[gib]          + ghs[0][b_][cc] + bhh[col];
            float zz = g_GI[gib + HH]     + ghs[1][b_][cc] + bhh[HH + col];
            float ghn = ghs[2][b_][cc] + bhh[2 * HH + col];
            float gin = g_GI[gib + 2 * HH];
            float r = 1.f / (1.f + expf(-rr));
            float z = 1.f / (1.f + expf(-zz));
            float n = tanhf(gin + r * ghn);
            float hp = g_h[cur][b_ * HH + col];
            float hv = (1.f - z) * n + z * hp;
            g_h[nxt][b_ * HH + col] = hv;
            __nv_bfloat16 hhi = __float2bfloat16(hv);
            g_hb_hi[nxt][b_ * HH + col] = hhi;
            g_hb_lo[nxt][b_ * HH + col] = __float2bfloat16(hv - __bfloat162float(hhi));
            g_HS[(size_t)(t * BB + b_) * HH + col] = hhi;
            if (t == TT - 1) dout[(size_t)BT * VV + b_ * HH + col] = hv;  // decoder_hidden
        }

        // grid barrier (release: fence + arrive; acquire: spin + fence)
        __threadfence();
        __syncthreads();
        if (tid == 0) {
            atomicAdd(&g_bar, 1u);
            unsigned target = (unsigned)(t + 1) * gridDim.x;
            while (atomicAdd(&g_bar, 0u) < target) {}
            __threadfence();
        }
        __syncthreads();
    }
}

// ---------------- kernel 5: classifier GEMM (single bf16) ---------------------
// logits = HS @ fc_w^T + fc_b -> d_out in (b,t,v) layout  (M=2048, N=32000)
__global__ void __launch_bounds__(256) k_gemm_fc(const float* __restrict__ bias,
                                                 float* __restrict__ Cout) {
    __shared__ unsigned AsU[128 * 17];
    __shared__ unsigned BsU[128 * 17];

    const int tid  = threadIdx.x;
    const int warp = tid >> 5, lane = tid & 31;
    const int wm = warp >> 1, wn = warp & 1;
    const int group = lane >> 2, tig = lane & 3;

    const unsigned* Ag = reinterpret_cast<const unsigned*>(g_HS)  + (size_t)blockIdx.x * 128 * K2H;
    const unsigned* Bg = reinterpret_cast<const unsigned*>(g_fcw) + (size_t)blockIdx.y * 128 * K2H;

    float c[2][8][4];
#pragma unroll
    for (int mt = 0; mt < 2; mt++)
#pragma unroll
        for (int nt = 0; nt < 8; nt++)
#pragma unroll
            for (int q = 0; q < 4; q++) c[mt][nt][q] = 0.f;

    for (int k0 = 0; k0 < K2H; k0 += 16) {
#pragma unroll
        for (int q = 0; q < 8; q++) {
            int idx = tid + q * 256;
            int r = idx >> 4, cw = idx & 15;
            AsU[r * 17 + cw] = Ag[(size_t)r * K2H + k0 + cw];
            BsU[r * 17 + cw] = Bg[(size_t)r * K2H + k0 + cw];
        }
        __syncthreads();
#pragma unroll
        for (int kk = 0; kk < 2; kk++) {
            int k2 = kk * 8;
            unsigned a[2][4], b[8][2];
#pragma unroll
            for (int mt = 0; mt < 2; mt++) {
                int r0 = (wm * 32 + mt * 16 + group) * 17 + k2 + tig;
                a[mt][0] = AsU[r0];
                a[mt][1] = AsU[r0 + 8 * 17];
                a[mt][2] = AsU[r0 + 4];
                a[mt][3] = AsU[r0 + 8 * 17 + 4];
            }
#pragma unroll
            for (int nt = 0; nt < 8; nt++) {
                int r = (wn * 64 + nt * 8 + group) * 17 + k2 + tig;
                b[nt][0] = BsU[r];
                b[nt][1] = BsU[r + 4];
            }
#pragma unroll
            for (int mt = 0; mt < 2; mt++)
#pragma unroll
                for (int nt = 0; nt < 8; nt++) mma16816(c[mt][nt], a[mt], b[nt]);
        }
        __syncthreads();
    }

#pragma unroll
    for (int mt = 0; mt < 2; mt++)
#pragma unroll
        for (int nt = 0; nt < 8; nt++) {
            int row = blockIdx.x * 128 + wm * 32 + mt * 16 + group;
            int col = blockIdx.y * 128 + wn * 64 + nt * 8 + tig * 2;
            float b0v = bias[col], b1v = bias[col + 1];
            int t0 = row >> 5, b0_ = row & 31;
            size_t base0 = ((size_t)b0_ * TT + t0) * VV + col;
            *reinterpret_cast<float2*>(Cout + base0) =
                make_float2(c[mt][nt][0] + b0v, c[mt][nt][1] + b1v);
            int row8 = row + 8;
            int t8 = row8 >> 5, b8_ = row8 & 31;
            size_t base8 = ((size_t)b8_ * TT + t8) * VV + col;
            *reinterpret_cast<float2*>(Cout + base8) =
                make_float2(c[mt][nt][2] + b0v, c[mt][nt][3] + b1v);
        }
}

// ---------------- kernel 6: in-place log_softmax per (b,t) row ----------------
__global__ void __launch_bounds__(256) k_lse(float* __restrict__ out) {
    int r = blockIdx.x;                       // r = b*64 + t  (matches (b,t,v) layout)
    float* row = out + (size_t)r * VV;
    int tid = threadIdx.x;

    float m = -INFINITY, s = 0.f;
    for (int v = tid; v < VV; v += 256) {
        float x = row[v];
        float nm = fmaxf(m, x);
        s = s * expf(m - nm) + expf(x - nm);
        m = nm;
    }
    __shared__ float sm[256], ss[256];
    sm[tid] = m; ss[tid] = s;
    __syncthreads();
    for (int o = 128; o > 0; o >>= 1) {
        if (tid < o) {
            float m2 = sm[tid + o], s2 = ss[tid + o];
            float nm = fmaxf(sm[tid], m2);
            ss[tid] = ss[tid] * expf(sm[tid] - nm) + s2 * expf(m2 - nm);
            sm[tid] = nm;
        }
        __syncthreads();
    }
    float lse = sm[0] + logf(ss[0]);
    for (int v = tid; v < VV; v += 256) row[v] -= lse;
}

// ---------------- launch ----------------
extern "C" void kernel_launch(void* const* d_in, const int* in_sizes, int n_in,
                              void* d_out, int out_size) {
    (void)in_sizes; (void)n_in; (void)out_size;
    const float* ench = (const float*)d_in[1];   // encoder_hidden [1,B,H]
    const int*   tgt  = (const int*)d_in[2];     // target [B,64] (dtype auto-detected)
    const float* emb  = (const float*)d_in[3];   // [V,H]
    const float* Wih  = (const float*)d_in[4];   // [3H,H]
    const float* Whh  = (const float*)d_in[5];   // [3H,H]
    const float* bih  = (const float*)d_in[6];   // [3H]
    const float* bhh  = (const float*)d_in[7];   // [3H]
    const float* fcw  = (const float*)d_in[8];   // [V,H]
    const float* fcb  = (const float*)d_in[9];   // [V]
    float* out = (float*)d_out;

    // 0. canonicalize tokens (dtype-detect + clamp) and reset grid barrier
    k_tok<<<1, 256>>>(tgt);
    // 1. weights -> bf16 hi/lo splits
    k_convert<<<2048, 256>>>(Wih, Whh, fcw);
    // 2. embedding gather + relu (hi/lo split) and h0 init
    k_embed<<<BT + BB, 256>>>(emb, ench);
    // 3. GI = X @ W_ih^T + b_ih   (split-bf16, near-fp32 precision)
    {
        dim3 g(BT / 128, TH / 128);
        k_gemm_gi<<<g, 256>>>(bih);
    }
    // 4. sequential GRU recurrence (persistent, 64 blocks, split-bf16 gh)
    k_recurrent<<<64, 128>>>(bhh, out);
    // 5. logits = HS @ fc_w^T + fc_b -> d_out (b,t,v)
    {
        dim3 g(BT / 128, VV / 128);
        k_gemm_fc<<<g, 256>>>(fcb, out);
    }
    // 6. in-place log_softmax per row
    k_lse<<<BT, 256>>>(out);
}